// round 1
// baseline (speedup 1.0000x reference)
#include <cuda_runtime.h>
#include <cooperative_groups.h>
#include <cstdint>

namespace cg = cooperative_groups;

#define BATCH 8
#define NPTS  32768
#define SPTS  512
#define GRP   32
#define BIGF  1e10f
#define R2F   0.04f

#define CLUSTER      8
#define FPS_THREADS  512
#define PTS_BLK      (NPTS / CLUSTER)        // 4096
#define PPT          (PTS_BLK / FPS_THREADS) // 8

#define CPT        32                         // centroids per block (ball query)
#define BQ_THREADS 256
#define CAP        128                        // max in-radius candidates kept

#define COMB_ELEMS (BATCH * SPTS * (GRP + 1) * 3)  // 405504
#define CENT_ELEMS (BATCH * SPTS * 3)              // 12288

// Scratch: padded float4 copy of xyz for vectorized loads (allowed: __device__ global)
__device__ float4 g_xyz4[BATCH * NPTS];

// ---------------------------------------------------------------------------
// Kernel 0: pack xyz [B,N,3] -> float4 array
// ---------------------------------------------------------------------------
__global__ void pad_kernel(const float* __restrict__ xyz) {
    int i = blockIdx.x * blockDim.x + threadIdx.x;
    if (i < BATCH * NPTS) {
        g_xyz4[i] = make_float4(xyz[3 * i], xyz[3 * i + 1], xyz[3 * i + 2], 0.f);
    }
}

// ---------------------------------------------------------------------------
// Kernel 1: FPS. One 8-CTA cluster per batch. Points live in registers.
// Per iteration: min-update dist, block argmax, cluster all-to-all candidate
// exchange via DSMEM, winner = next centroid. Writes centroids_xyz to d_out.
// ---------------------------------------------------------------------------
__global__ void __cluster_dims__(CLUSTER, 1, 1) __launch_bounds__(FPS_THREADS, 1)
fps_kernel(const int* __restrict__ finit, float* __restrict__ out_cent) {
    cg::cluster_group cluster = cg::this_cluster();
    const unsigned rank = blockIdx.x % CLUSTER;
    const int b   = blockIdx.x / CLUSTER;
    const int tid = threadIdx.x;
    const int lane = tid & 31, wid = tid >> 5;
    const float4* __restrict__ xb = g_xyz4 + b * NPTS;

    // register-resident points + running min distance
    float px[PPT], py[PPT], pz[PPT], dd[PPT];
    const int pid0 = rank * PTS_BLK + tid;
#pragma unroll
    for (int i = 0; i < PPT; i++) {
        float4 p = xb[pid0 + i * FPS_THREADS];
        px[i] = p.x; py[i] = p.y; pz[i] = p.z; dd[i] = BIGF;
    }

    // DSMEM exchange buffers (double buffered), block-reduce scratch, broadcast
    __shared__ float sv[2][CLUSTER]; __shared__ int si[2][CLUSTER];
    __shared__ float sx[2][CLUSTER], sy[2][CLUSTER], sz[2][CLUSTER];
    __shared__ float rv[16]; __shared__ int ri[16];
    __shared__ float rx[16], ry[16], rz[16];
    __shared__ float bcx, bcy, bcz;

    int far = finit[b];
    float4 c0 = xb[far];
    float cx = c0.x, cy = c0.y, cz = c0.z;

    for (int s = 0; s < SPTS; s++) {
        if (rank == 0 && tid == 0) {
            float* o = out_cent + (size_t)(b * SPTS + s) * 3;
            o[0] = cx; o[1] = cy; o[2] = cz;
        }

        // min-update + thread-local argmax (ascending point index => strict >
        // keeps the first/lowest-index max, matching jnp.argmax)
        float bv = -1.f; int bi = 0x7fffffff; float bx = 0.f, by = 0.f, bz = 0.f;
#pragma unroll
        for (int i = 0; i < PPT; i++) {
            float dx = px[i] - cx, dy = py[i] - cy, dz = pz[i] - cz;
            // NO fma contraction: match XLA's mul+add lowering exactly
            float sq = __fadd_rn(__fadd_rn(__fmul_rn(dx, dx), __fmul_rn(dy, dy)),
                                 __fmul_rn(dz, dz));
            float nd = fminf(dd[i], sq);
            dd[i] = nd;
            if (nd > bv) { bv = nd; bi = pid0 + i * FPS_THREADS; bx = px[i]; by = py[i]; bz = pz[i]; }
        }

        // warp argmax reduce (tie -> smaller index)
#pragma unroll
        for (int off = 16; off; off >>= 1) {
            float ov = __shfl_down_sync(0xffffffffu, bv, off);
            int   oi = __shfl_down_sync(0xffffffffu, bi, off);
            float ox = __shfl_down_sync(0xffffffffu, bx, off);
            float oy = __shfl_down_sync(0xffffffffu, by, off);
            float oz = __shfl_down_sync(0xffffffffu, bz, off);
            if (ov > bv || (ov == bv && oi < bi)) { bv = ov; bi = oi; bx = ox; by = oy; bz = oz; }
        }
        if (lane == 0) { rv[wid] = bv; ri[wid] = bi; rx[wid] = bx; ry[wid] = by; rz[wid] = bz; }
        __syncthreads();

        const int par = s & 1;
        if (wid == 0) {
            float v  = (lane < 16) ? rv[lane] : -2.f;
            int   ii = (lane < 16) ? ri[lane] : 0x7fffffff;
            float x_ = (lane < 16) ? rx[lane] : 0.f;
            float y_ = (lane < 16) ? ry[lane] : 0.f;
            float z_ = (lane < 16) ? rz[lane] : 0.f;
#pragma unroll
            for (int off = 8; off; off >>= 1) {
                float ov = __shfl_down_sync(0xffffffffu, v, off);
                int   oi = __shfl_down_sync(0xffffffffu, ii, off);
                float ox = __shfl_down_sync(0xffffffffu, x_, off);
                float oy = __shfl_down_sync(0xffffffffu, y_, off);
                float oz = __shfl_down_sync(0xffffffffu, z_, off);
                if (ov > v || (ov == v && oi < ii)) { v = ov; ii = oi; x_ = ox; y_ = oy; z_ = oz; }
            }
            if (lane == 0) {
                // write my block candidate into slot[rank] of every cluster CTA
#pragma unroll
                for (int r = 0; r < CLUSTER; r++) {
                    *(float*)cluster.map_shared_rank((void*)&sv[par][rank], r) = v;
                    *(int*)  cluster.map_shared_rank((void*)&si[par][rank], r) = ii;
                    *(float*)cluster.map_shared_rank((void*)&sx[par][rank], r) = x_;
                    *(float*)cluster.map_shared_rank((void*)&sy[par][rank], r) = y_;
                    *(float*)cluster.map_shared_rank((void*)&sz[par][rank], r) = z_;
                }
            }
        }
        cluster.sync();

        // pick cluster winner locally
        if (wid == 0) {
            float v  = (lane < CLUSTER) ? sv[par][lane] : -2.f;
            int   ii = (lane < CLUSTER) ? si[par][lane] : 0x7fffffff;
            float x_ = (lane < CLUSTER) ? sx[par][lane] : 0.f;
            float y_ = (lane < CLUSTER) ? sy[par][lane] : 0.f;
            float z_ = (lane < CLUSTER) ? sz[par][lane] : 0.f;
#pragma unroll
            for (int off = 4; off; off >>= 1) {
                float ov = __shfl_down_sync(0xffffffffu, v, off);
                int   oi = __shfl_down_sync(0xffffffffu, ii, off);
                float ox = __shfl_down_sync(0xffffffffu, x_, off);
                float oy = __shfl_down_sync(0xffffffffu, y_, off);
                float oz = __shfl_down_sync(0xffffffffu, z_, off);
                if (ov > v || (ov == v && oi < ii)) { v = ov; ii = oi; x_ = ox; y_ = oy; z_ = oz; }
            }
            if (lane == 0) { bcx = x_; bcy = y_; bcz = z_; }
        }
        __syncthreads();
        cx = bcx; cy = bcy; cz = bcz;
    }
}

// ---------------------------------------------------------------------------
// Kernel 2: ball query + group + relative coords. 32 centroids per CTA,
// centroids in registers, stream points once. Stable (dist,idx) selection
// via packed uint64 keys; index-ordered out-of-radius padding.
// ---------------------------------------------------------------------------
__global__ void __launch_bounds__(BQ_THREADS, 1)
ball_kernel(const float* __restrict__ cent, float* __restrict__ outc) {
    const int b  = blockIdx.x >> 4;               // 16 groups of 32 per batch
    const int s0 = (blockIdx.x & 15) * CPT;
    const int tid = threadIdx.x;
    const int lane = tid & 31, wid = tid >> 5;

    __shared__ float4 sc[CPT];
    __shared__ int cnt[CPT];
    __shared__ unsigned long long keys[CPT][CAP];
    __shared__ int sel[CPT][GRP];

    if (tid < CPT) {
        cnt[tid] = 0;
        const float* c = cent + (size_t)(b * SPTS + s0 + tid) * 3;
        sc[tid] = make_float4(c[0], c[1], c[2], 0.f);
    }
    __syncthreads();

    float cxr[CPT], cyr[CPT], czr[CPT];
#pragma unroll
    for (int c = 0; c < CPT; c++) { float4 t = sc[c]; cxr[c] = t.x; cyr[c] = t.y; czr[c] = t.z; }

    const float4* __restrict__ xb = g_xyz4 + b * NPTS;

    for (int pid = tid; pid < NPTS; pid += BQ_THREADS) {
        float4 p = xb[pid];
#pragma unroll
        for (int c = 0; c < CPT; c++) {
            float dx = p.x - cxr[c], dy = p.y - cyr[c], dz = p.z - czr[c];
            float sq = __fadd_rn(__fadd_rn(__fmul_rn(dx, dx), __fmul_rn(dy, dy)),
                                 __fmul_rn(dz, dz));
            if (sq <= R2F) {
                int pos = atomicAdd(&cnt[c], 1);
                if (pos < CAP)
                    keys[c][pos] = ((unsigned long long)__float_as_uint(sq) << 32) | (unsigned)pid;
            }
        }
    }
    __syncthreads();

    // selection: warp w handles centroids [w*4, w*4+4)
    for (int k = 0; k < CPT / 8; k++) {
        const int c = wid * (CPT / 8) + k;
        const int m = min(cnt[c], CAP);
        const int K = min(m, GRP);

        unsigned long long kk[CAP / 32];
#pragma unroll
        for (int j = 0; j < CAP / 32; j++) {
            int pos = lane + 32 * j;
            kk[j] = (pos < m) ? keys[c][pos] : 0xFFFFFFFFFFFFFFFFull;
        }
        for (int t = 0; t < K; t++) {
            unsigned long long lm = kk[0];
#pragma unroll
            for (int j = 1; j < CAP / 32; j++) lm = (kk[j] < lm) ? kk[j] : lm;
#pragma unroll
            for (int off = 16; off; off >>= 1) {
                unsigned long long o = __shfl_xor_sync(0xffffffffu, lm, off);
                lm = (o < lm) ? o : lm;
            }
#pragma unroll
            for (int j = 0; j < CAP / 32; j++) if (kk[j] == lm) kk[j] = 0xFFFFFFFFFFFFFFFFull;
            if (lane == 0) sel[c][t] = (int)(unsigned)(lm & 0xFFFFFFFFull);
        }

        // padding: smallest indices with dist > r^2 (stable-sort-of-BIG semantics)
        int need = GRP - K;
        int base = 0;
        while (need > 0) {
            int id = base + lane;
            bool oor = false;
            if (id < NPTS) {
                float4 p = xb[id];
                float dx = p.x - cxr[c], dy = p.y - cyr[c], dz = p.z - czr[c];
                float sq = __fadd_rn(__fadd_rn(__fmul_rn(dx, dx), __fmul_rn(dy, dy)),
                                     __fmul_rn(dz, dz));
                oor = (sq > R2F);
            }
            unsigned msk = __ballot_sync(0xffffffffu, oor);
            int r = __popc(msk & ((1u << lane) - 1u));
            if (oor && r < need) sel[c][GRP - need + r] = id;
            int take = min(__popc(msk), need);
            need -= take;
            base += 32;
        }
    }
    __syncthreads();

    // output: combined[b,s,0,:] = centroid; combined[b,s,1+g,:] = p_g - centroid
    for (int k = 0; k < CPT / 8; k++) {
        const int c = wid * (CPT / 8) + k;
        const int s = s0 + c;
        float4 cc = sc[c];
        float* ob = outc + (size_t)((b * SPTS + s) * (GRP + 1)) * 3;
        if (lane == 0) { ob[0] = cc.x; ob[1] = cc.y; ob[2] = cc.z; }
        int idx = sel[c][lane];
        float4 p = xb[idx];
        float* og = ob + (size_t)(1 + lane) * 3;
        og[0] = p.x - cc.x; og[1] = p.y - cc.y; og[2] = p.z - cc.z;
    }
}

// ---------------------------------------------------------------------------
extern "C" void kernel_launch(void* const* d_in, const int* in_sizes, int n_in,
                              void* d_out, int out_size) {
    const float* xyz   = (const float*)d_in[0];
    const int*   finit = (const int*)d_in[1];
    float* out  = (float*)d_out;
    float* comb = out;                 // [B,S,33,3]
    float* cent = out + COMB_ELEMS;    // [B,S,3]

    pad_kernel<<<(BATCH * NPTS + 255) / 256, 256>>>(xyz);
    fps_kernel<<<BATCH * CLUSTER, FPS_THREADS>>>(finit, cent);
    ball_kernel<<<BATCH * (SPTS / CPT), BQ_THREADS>>>(cent, comb);
}

// round 2
// speedup vs baseline: 1.0639x; 1.0639x over previous
#include <cuda_runtime.h>
#include <cstdint>

#define BATCH 8
#define NPTS  32768
#define SPTS  512
#define GRP   32
#define BIGF  1e10f
#define R2F   0.04f

#define CLUSTER      8
#define FPS_THREADS  512
#define PTS_BLK      (NPTS / CLUSTER)        // 4096
#define PPT          (PTS_BLK / FPS_THREADS) // 8

#define CPT        32
#define BQ_THREADS 256
#define CAP        128

#define COMB_ELEMS (BATCH * SPTS * (GRP + 1) * 3)  // 405504

__device__ float4 g_xyz4[BATCH * NPTS];

// ---------------------------------------------------------------------------
// helpers
// ---------------------------------------------------------------------------
__device__ __forceinline__ unsigned smem_u32(const void* p) {
    unsigned a;
    asm("{ .reg .u64 t; cvta.to.shared.u64 t, %1; cvt.u32.u64 %0, t; }" : "=r"(a) : "l"(p));
    return a;
}
__device__ __forceinline__ unsigned redux_max_u32(unsigned v) {
    unsigned r; asm("redux.sync.max.u32 %0, %1, 0xffffffff;" : "=r"(r) : "r"(v)); return r;
}
__device__ __forceinline__ unsigned redux_min_u32(unsigned v) {
    unsigned r; asm("redux.sync.min.u32 %0, %1, 0xffffffff;" : "=r"(r) : "r"(v)); return r;
}
__device__ __forceinline__ unsigned mapa_u32(unsigned laddr, unsigned rank) {
    unsigned r; asm("mapa.shared::cluster.u32 %0, %1, %2;" : "=r"(r) : "r"(laddr), "r"(rank));
    return r;
}

#define MBAR_INIT(addr, cnt) \
    asm volatile("mbarrier.init.shared.b64 [%0], %1;" :: "r"(addr), "r"(cnt) : "memory")

#define MBAR_ARRIVE_REMOTE_REL(raddr) \
    asm volatile("mbarrier.arrive.release.cluster.shared::cluster.b64 _, [%0];" \
                 :: "r"(raddr) : "memory")

#define MBAR_WAIT_PARITY_ACQ_CLUSTER(mbar, parity) do {                            \
    unsigned _m = (mbar), _p = (parity), _d;                                       \
    asm volatile("{\n\t.reg .pred p;\n\t"                                          \
        "mbarrier.try_wait.parity.acquire.cluster.shared::cta.b64 p, [%1], %2;\n\t"\
        "selp.b32 %0, 1, 0, p;\n\t}"                                               \
        : "=r"(_d) : "r"(_m), "r"(_p) : "memory");                                 \
    if (!_d) {                                                                     \
        asm volatile("{\n\t.reg .pred P1;\n"                                       \
            "WL_%=:\n\t"                                                           \
            "mbarrier.try_wait.parity.acquire.cluster.shared::cta.b64 P1, [%0], %1;\n\t" \
            "@P1 bra.uni WD_%=;\n\t"                                               \
            "bra.uni WL_%=;\n"                                                     \
            "WD_%=:\n\t}" :: "r"(_m), "r"(_p) : "memory");                         \
    }                                                                              \
} while (0)

#define CLUSTER_SYNC_ASM() do {                                        \
    asm volatile("barrier.cluster.arrive.aligned;" ::: "memory");      \
    asm volatile("barrier.cluster.wait.aligned;" ::: "memory");        \
} while (0)

// ---------------------------------------------------------------------------
// Kernel 0: pack xyz [B,N,3] -> float4
// ---------------------------------------------------------------------------
__global__ void pad_kernel(const float* __restrict__ xyz) {
    int i = blockIdx.x * blockDim.x + threadIdx.x;
    if (i < BATCH * NPTS) {
        g_xyz4[i] = make_float4(xyz[3 * i], xyz[3 * i + 1], xyz[3 * i + 2], 0.f);
    }
}

// ---------------------------------------------------------------------------
// Kernel 1: FPS — 8-CTA cluster per batch, register-resident points,
// REDUX argmax, mbarrier DSMEM candidate exchange (no cluster.sync per iter).
// ---------------------------------------------------------------------------
struct __align__(16) Slot { unsigned v; unsigned pid; float x; float y; float z; unsigned pad[3]; };

__global__ void __cluster_dims__(CLUSTER, 1, 1) __launch_bounds__(FPS_THREADS, 1)
fps_kernel(const int* __restrict__ finit, float* __restrict__ out_cent) {
    const int tid  = threadIdx.x;
    const int lane = tid & 31, wid = tid >> 5;
    unsigned rank;
    asm("mov.u32 %0, %%cluster_ctarank;" : "=r"(rank));
    const int b = blockIdx.x / CLUSTER;
    const float4* __restrict__ xb = g_xyz4 + b * NPTS;

    __shared__ Slot exch[2][CLUSTER];
    __shared__ unsigned long long bars[2];
    __shared__ unsigned svb[16], spid[16];
    __shared__ float sx[16], sy[16], sz[16];
    __shared__ float bcx, bcy, bcz;

    if (tid == 0) {
        MBAR_INIT(smem_u32(&bars[0]), CLUSTER);
        MBAR_INIT(smem_u32(&bars[1]), CLUSTER);
    }
    __syncthreads();
    CLUSTER_SYNC_ASM();   // mbarrier init visible cluster-wide before any remote arrive

    // register-resident points
    float px[PPT], py[PPT], pz[PPT], dd[PPT];
    const int pid0 = rank * PTS_BLK + tid;
#pragma unroll
    for (int i = 0; i < PPT; i++) {
        float4 p = xb[pid0 + i * FPS_THREADS];
        px[i] = p.x; py[i] = p.y; pz[i] = p.z; dd[i] = BIGF;
    }

    float4 c0 = xb[finit[b]];
    float cx = c0.x, cy = c0.y, cz = c0.z;

    for (int s = 0; s < SPTS; s++) {
        if (rank == 0 && tid == 0) {
            float* o = out_cent + (size_t)(b * SPTS + s) * 3;
            o[0] = cx; o[1] = cy; o[2] = cz;
        }
        if (s == SPTS - 1) break;

        // ---- per-point min-update + thread argmax (exact mul/add rounding) ----
        float bv = -1.f; unsigned bpid = 0;
#pragma unroll
        for (int i = 0; i < PPT; i++) {
            float dx = px[i] - cx, dy = py[i] - cy, dz = pz[i] - cz;
            float sq = __fadd_rn(__fadd_rn(__fmul_rn(dx, dx), __fmul_rn(dy, dy)),
                                 __fmul_rn(dz, dz));
            float nd = fminf(dd[i], sq);
            dd[i] = nd;
            if (nd > bv) { bv = nd; bpid = (unsigned)(pid0 + i * FPS_THREADS); }
        }

        // ---- warp argmax via REDUX (tie -> smaller pid) ----
        unsigned vb   = __float_as_uint(bv);                 // bv >= 0 always
        unsigned vmax = redux_max_u32(vb);
        unsigned pidw = redux_min_u32((vb == vmax) ? bpid : 0xffffffffu);

        // owner lane reconstructs winner coords from its registers
        if ((pidw & 511u) == (unsigned)tid) {
            int i = (pidw >> 9) & 7;
            float ox = px[0], oy = py[0], oz = pz[0];
#pragma unroll
            for (int j = 1; j < PPT; j++)
                if (i == j) { ox = px[j]; oy = py[j]; oz = pz[j]; }
            svb[wid] = vmax; spid[wid] = pidw;
            sx[wid] = ox; sy[wid] = oy; sz[wid] = oz;
        }
        __syncthreads();

        const int bb = s & 1;
        const unsigned ph = (unsigned)((s >> 1) & 1);

        if (wid == 0) {
            // ---- block argmax over 16 warp winners ----
            unsigned v2  = (lane < 16) ? svb[lane] : 0u;
            unsigned vm2 = redux_max_u32(v2);
            unsigned p2  = (lane < 16 && v2 == vm2) ? spid[lane] : 0xffffffffu;
            unsigned pw2 = redux_min_u32(p2);
            unsigned msk = __ballot_sync(0xffffffffu, lane < 16 && spid[lane] == pw2);
            int src = __ffs(msk) - 1;
            float x = sx[src], y = sy[src], z = sz[src];

            // ---- broadcast candidate to all 8 cluster CTAs (lane r -> rank r) ----
            if (lane < CLUSTER) {
                unsigned lslot = smem_u32(&exch[bb][rank]);
                unsigned rslot = mapa_u32(lslot, (unsigned)lane);
                asm volatile("st.shared::cluster.v4.b32 [%0], {%1,%2,%3,%4};"
                             :: "r"(rslot), "r"(vm2), "r"(pw2),
                                "r"(__float_as_uint(x)), "r"(__float_as_uint(y)) : "memory");
                asm volatile("st.shared::cluster.b32 [%0], %1;"
                             :: "r"(rslot + 16u), "r"(__float_as_uint(z)) : "memory");
                unsigned rbar = mapa_u32(smem_u32(&bars[bb]), (unsigned)lane);
                MBAR_ARRIVE_REMOTE_REL(rbar);
            }

            // ---- wait for all 8 candidates, cluster argmax ----
            MBAR_WAIT_PARITY_ACQ_CLUSTER(smem_u32(&bars[bb]), ph);

            unsigned v3  = (lane < CLUSTER) ? exch[bb][lane].v   : 0u;
            unsigned p3i = (lane < CLUSTER) ? exch[bb][lane].pid : 0xffffffffu;
            unsigned vm3 = redux_max_u32(v3);
            unsigned pw3 = redux_min_u32((lane < CLUSTER && v3 == vm3) ? p3i : 0xffffffffu);
            unsigned m3  = __ballot_sync(0xffffffffu, lane < CLUSTER && p3i == pw3);
            int src3 = __ffs(m3) - 1;
            if (lane == 0) {
                bcx = exch[bb][src3].x; bcy = exch[bb][src3].y; bcz = exch[bb][src3].z;
            }
        }
        __syncthreads();
        cx = bcx; cy = bcy; cz = bcz;
    }

    CLUSTER_SYNC_ASM();
}

// ---------------------------------------------------------------------------
// Kernel 2: ball query + group + relative coords (unchanged from R1, proven)
// ---------------------------------------------------------------------------
__global__ void __launch_bounds__(BQ_THREADS, 1)
ball_kernel(const float* __restrict__ cent, float* __restrict__ outc) {
    const int b  = blockIdx.x >> 4;
    const int s0 = (blockIdx.x & 15) * CPT;
    const int tid = threadIdx.x;
    const int lane = tid & 31, wid = tid >> 5;

    __shared__ float4 sc[CPT];
    __shared__ int cnt[CPT];
    __shared__ unsigned long long keys[CPT][CAP];
    __shared__ int sel[CPT][GRP];

    if (tid < CPT) {
        cnt[tid] = 0;
        const float* c = cent + (size_t)(b * SPTS + s0 + tid) * 3;
        sc[tid] = make_float4(c[0], c[1], c[2], 0.f);
    }
    __syncthreads();

    float cxr[CPT], cyr[CPT], czr[CPT];
#pragma unroll
    for (int c = 0; c < CPT; c++) { float4 t = sc[c]; cxr[c] = t.x; cyr[c] = t.y; czr[c] = t.z; }

    const float4* __restrict__ xb = g_xyz4 + b * NPTS;

    for (int pid = tid; pid < NPTS; pid += BQ_THREADS) {
        float4 p = xb[pid];
#pragma unroll
        for (int c = 0; c < CPT; c++) {
            float dx = p.x - cxr[c], dy = p.y - cyr[c], dz = p.z - czr[c];
            float sq = __fadd_rn(__fadd_rn(__fmul_rn(dx, dx), __fmul_rn(dy, dy)),
                                 __fmul_rn(dz, dz));
            if (sq <= R2F) {
                int pos = atomicAdd(&cnt[c], 1);
                if (pos < CAP)
                    keys[c][pos] = ((unsigned long long)__float_as_uint(sq) << 32) | (unsigned)pid;
            }
        }
    }
    __syncthreads();

    for (int k = 0; k < CPT / 8; k++) {
        const int c = wid * (CPT / 8) + k;
        const int m = min(cnt[c], CAP);
        const int K = min(m, GRP);

        unsigned long long kk[CAP / 32];
#pragma unroll
        for (int j = 0; j < CAP / 32; j++) {
            int pos = lane + 32 * j;
            kk[j] = (pos < m) ? keys[c][pos] : 0xFFFFFFFFFFFFFFFFull;
        }
        for (int t = 0; t < K; t++) {
            unsigned long long lm = kk[0];
#pragma unroll
            for (int j = 1; j < CAP / 32; j++) lm = (kk[j] < lm) ? kk[j] : lm;
#pragma unroll
            for (int off = 16; off; off >>= 1) {
                unsigned long long o = __shfl_xor_sync(0xffffffffu, lm, off);
                lm = (o < lm) ? o : lm;
            }
#pragma unroll
            for (int j = 0; j < CAP / 32; j++) if (kk[j] == lm) kk[j] = 0xFFFFFFFFFFFFFFFFull;
            if (lane == 0) sel[c][t] = (int)(unsigned)(lm & 0xFFFFFFFFull);
        }

        int need = GRP - K;
        int base = 0;
        while (need > 0) {
            int id = base + lane;
            bool oor = false;
            if (id < NPTS) {
                float4 p = xb[id];
                float dx = p.x - cxr[c], dy = p.y - cyr[c], dz = p.z - czr[c];
                float sq = __fadd_rn(__fadd_rn(__fmul_rn(dx, dx), __fmul_rn(dy, dy)),
                                     __fmul_rn(dz, dz));
                oor = (sq > R2F);
            }
            unsigned msk = __ballot_sync(0xffffffffu, oor);
            int r = __popc(msk & ((1u << lane) - 1u));
            if (oor && r < need) sel[c][GRP - need + r] = id;
            int take = min(__popc(msk), need);
            need -= take;
            base += 32;
        }
    }
    __syncthreads();

    for (int k = 0; k < CPT / 8; k++) {
        const int c = wid * (CPT / 8) + k;
        const int s = s0 + c;
        float4 cc = sc[c];
        float* ob = outc + (size_t)((b * SPTS + s) * (GRP + 1)) * 3;
        if (lane == 0) { ob[0] = cc.x; ob[1] = cc.y; ob[2] = cc.z; }
        int idx = sel[c][lane];
        float4 p = xb[idx];
        float* og = ob + (size_t)(1 + lane) * 3;
        og[0] = p.x - cc.x; og[1] = p.y - cc.y; og[2] = p.z - cc.z;
    }
}

// ---------------------------------------------------------------------------
extern "C" void kernel_launch(void* const* d_in, const int* in_sizes, int n_in,
                              void* d_out, int out_size) {
    const float* xyz   = (const float*)d_in[0];
    const int*   finit = (const int*)d_in[1];
    float* out  = (float*)d_out;
    float* comb = out;                 // [B,S,33,3]
    float* cent = out + COMB_ELEMS;    // [B,S,3]

    pad_kernel<<<(BATCH * NPTS + 255) / 256, 256>>>(xyz);
    fps_kernel<<<BATCH * CLUSTER, FPS_THREADS>>>(finit, cent);
    ball_kernel<<<BATCH * (SPTS / CPT), BQ_THREADS>>>(cent, comb);
}